// round 15
// baseline (speedup 1.0000x reference)
#include <cuda_runtime.h>
#include <cuda_bf16.h>
#include <cuda_fp16.h>
#include <cstdint>

#define D_MODEL 1024
#define N_HEADS 16
#define DK 64
#define BATCH 2
#define TSEQ 2048
#define MROWS (BATCH*TSEQ)   /* 4096 */
#define CHUNK 128
#define NCHUNK (TSEQ/CHUNK)  /* 16 */
#define NBH (BATCH*N_HEADS)  /* 32 */
#define KVE 72               /* KV ext cols: 64 + ksum + pad */

// ---------------- scratch (static device arrays; no allocation) ----------------
__device__ float g_kv[NBH*NCHUNK*DK*DK];
__device__ float g_ksum[NBH*NCHUNK*DK];
// fp16 GEMM operands (W pre-scaled by 32)
__device__ __half g_xh[MROWS*D_MODEL];
__device__ __half g_wh[4*D_MODEL*D_MODEL];
__device__ __half g_ah[MROWS*D_MODEL];
// fp16 attention operands (all single fp16)
__device__ __half g_qf[NBH*TSEQ*DK];
__device__ __half g_kf[NBH*TSEQ*DK];
__device__ __half g_vf[NBH*TSEQ*DK];
__device__ __half g_kvf[NBH*NCHUNK*DK*KVE];

__device__ __forceinline__ float phi_fn(float x) {
    return x > 0.f ? x + 1.f : __expf(x);
}
__device__ __forceinline__ uint32_t smem_to_u32(const void* smem_ptr) {
    uint32_t addr;
    asm("{ .reg .u64 tmp; cvta.to.shared.u64 tmp, %1; cvt.u32.u64 %0, tmp; }"
        : "=r"(addr) : "l"(smem_ptr));
    return addr;
}

// ---------------- mma / ldmatrix / cp.async primitives ----------------
__device__ __forceinline__ void mma16816h(float* d, const uint32_t* a, const uint32_t* b) {
    asm volatile(
        "mma.sync.aligned.m16n8k16.row.col.f32.f16.f16.f32 "
        "{%0,%1,%2,%3}, {%4,%5,%6,%7}, {%8,%9}, {%0,%1,%2,%3};"
        : "+f"(d[0]), "+f"(d[1]), "+f"(d[2]), "+f"(d[3])
        : "r"(a[0]), "r"(a[1]), "r"(a[2]), "r"(a[3]), "r"(b[0]), "r"(b[1]));
}
__device__ __forceinline__ void ldsm4(uint32_t* r, uint32_t addr) {
    asm volatile("ldmatrix.sync.aligned.m8n8.x4.shared.b16 {%0,%1,%2,%3}, [%4];"
        : "=r"(r[0]), "=r"(r[1]), "=r"(r[2]), "=r"(r[3]) : "r"(addr));
}
__device__ __forceinline__ void ldsm4t(uint32_t* r, uint32_t addr) {
    asm volatile("ldmatrix.sync.aligned.m8n8.x4.trans.shared.b16 {%0,%1,%2,%3}, [%4];"
        : "=r"(r[0]), "=r"(r[1]), "=r"(r[2]), "=r"(r[3]) : "r"(addr));
}
__device__ __forceinline__ void ldsm2t(uint32_t* r, uint32_t addr) {
    asm volatile("ldmatrix.sync.aligned.m8n8.x2.trans.shared.b16 {%0,%1}, [%2];"
        : "=r"(r[0]), "=r"(r[1]) : "r"(addr));
}
#define CP_ASYNC16(dst, src) \
    asm volatile("cp.async.cg.shared.global [%0], [%1], 16;" :: "r"(dst), "l"(src))
#define CP_COMMIT() asm volatile("cp.async.commit_group;" ::: "memory")
#define CP_WAIT1()  asm volatile("cp.async.wait_group 1;" ::: "memory")
#define CP_WAIT0()  asm volatile("cp.async.wait_group 0;" ::: "memory")

__device__ __forceinline__ uint32_t pack_h(float a, float b) {
    __half2 p = __floats2half2_rn(a, b);
    return *reinterpret_cast<uint32_t*>(&p);
}
#define SWZ128(off) ((uint32_t)(off) ^ ((((uint32_t)(off)) >> 3) & 0x70))

// ---------------- merged input conversion ----------------
__global__ __launch_bounds__(256) void split_all_kernel(
    const float* __restrict__ x,
    const float* __restrict__ w0, const float* __restrict__ w1,
    const float* __restrict__ w2, const float* __restrict__ w3)
{
    const int per = D_MODEL*D_MODEL/4;          // 262144
    int i = blockIdx.x * 256 + threadIdx.x;
    if (i < MROWS*D_MODEL/4) {
        float4 v = ((const float4*)x)[i];
        ((__half2*)(g_xh + 4*(size_t)i))[0] = __floats2half2_rn(v.x, v.y);
        ((__half2*)(g_xh + 4*(size_t)i))[1] = __floats2half2_rn(v.z, v.w);
    } else {
        int j = i - MROWS*D_MODEL/4;
        int sel = j >> 18, loc = j & (per - 1);
        const float* src = (sel == 0) ? w0 : (sel == 1) ? w1 : (sel == 2) ? w2 : w3;
        float4 v = ((const float4*)src)[loc];
        size_t o = (size_t)sel * D_MODEL * D_MODEL + 4*(size_t)loc;
        ((__half2*)(g_wh + o))[0] = __floats2half2_rn(v.x*32.f, v.y*32.f);
        ((__half2*)(g_wh + o))[1] = __floats2half2_rn(v.z*32.f, v.w*32.f);
    }
}

// ---------------- fp16 GEMM: BK=64, 3-stage, SW128, 2 CTAs/SM ----------------
#define TILE_B (128*128)
#define STAGE_B (2*TILE_B)
#define GEMM_SMEM (3*STAGE_B)       /* 98304 */
#define NSTG 16

__device__ __forceinline__ void gemm_body(
    int ep, const __half* __restrict__ Xh,
    const float* __restrict__ bias, float* __restrict__ outp, char* smem)
{
    const uint32_t sb = smem_to_u32(smem);
    const int tid = threadIdx.x;
    const int lane = tid & 31, wid = tid >> 5;
    const int wm = wid & 1, wn = wid >> 1;
    const int m0 = blockIdx.y * 128;
    const int n0 = blockIdx.x * 128;

    const __half* Wh = g_wh + (size_t)ep * D_MODEL * D_MODEL;

    float acc[4][4][4];
    #pragma unroll
    for (int i = 0; i < 4; i++)
        #pragma unroll
        for (int j = 0; j < 4; j++)
            #pragma unroll
            for (int l = 0; l < 4; l++) acc[i][j][l] = 0.f;

    const int lr = tid >> 2, lu = (tid & 3) * 2;
    const uint32_t d00 = SWZ128(lr*128 + lu*16),        d01 = SWZ128(lr*128 + (lu+1)*16);
    const uint32_t d10 = SWZ128((lr+64)*128 + lu*16),   d11 = SWZ128((lr+64)*128 + (lu+1)*16);

    auto load_stage = [&](int buf, int k0) {
        uint32_t base = sb + buf * STAGE_B;
        CP_ASYNC16(base + d00, Xh + (size_t)(m0 + lr)*D_MODEL + k0 + lu*8);
        CP_ASYNC16(base + d01, Xh + (size_t)(m0 + lr)*D_MODEL + k0 + lu*8 + 8);
        CP_ASYNC16(base + d10, Xh + (size_t)(m0 + lr + 64)*D_MODEL + k0 + lu*8);
        CP_ASYNC16(base + d11, Xh + (size_t)(m0 + lr + 64)*D_MODEL + k0 + lu*8 + 8);
        base += TILE_B;
        CP_ASYNC16(base + d00, Wh + (size_t)(n0 + lr)*D_MODEL + k0 + lu*8);
        CP_ASYNC16(base + d01, Wh + (size_t)(n0 + lr)*D_MODEL + k0 + lu*8 + 8);
        CP_ASYNC16(base + d10, Wh + (size_t)(n0 + lr + 64)*D_MODEL + k0 + lu*8);
        CP_ASYNC16(base + d11, Wh + (size_t)(n0 + lr + 64)*D_MODEL + k0 + lu*8 + 8);
        CP_COMMIT();
    };

    load_stage(0, 0);
    load_stage(1, 64);

    for (int kc = 0; kc < NSTG; kc++) {
        if (kc < NSTG-1) { CP_WAIT1(); } else { CP_WAIT0(); }
        __syncthreads();
        if (kc + 2 < NSTG) load_stage((kc + 2) % 3, (kc + 2) * 64);

        const uint32_t base = sb + (kc % 3) * STAGE_B;
        #pragma unroll
        for (int ks = 0; ks < 4; ks++) {
            uint32_t ah[4][4], bh[2][4];
            #pragma unroll
            for (int mt = 0; mt < 4; mt++) {
                const int rA = wm*64 + mt*16 + (lane & 15);
                const uint32_t offA = SWZ128(rA*128 + ((lane >> 4) + 2*ks)*16);
                ldsm4(ah[mt], base + offA);
            }
            #pragma unroll
            for (int op = 0; op < 2; op++) {
                const int rB = wn*32 + op*16 + ((lane >> 4) << 3) + (lane & 7);
                const uint32_t offB = SWZ128(rB*128 + (((lane >> 3) & 1) + 2*ks)*16);
                ldsm4(bh[op], base + TILE_B + offB);
            }
            #pragma unroll
            for (int mt = 0; mt < 4; mt++)
                #pragma unroll
                for (int nt = 0; nt < 4; nt++) {
                    const uint32_t* bhp = &bh[nt >> 1][(nt & 1) * 2];
                    mma16816h(acc[mt][nt], ah[mt], bhp);
                }
        }
    }
    __syncthreads();

    // ---- epilogue (acc is 32x scaled) ----
    const float INV32 = 1.f/32.f;
    const int m_base = m0 + wm*64;
    #pragma unroll
    for (int mt = 0; mt < 4; mt++) {
        #pragma unroll
        for (int nt = 0; nt < 4; nt++) {
            const int n = n0 + wn*32 + nt*8 + (lane & 3)*2;
            const float b0v = bias[n], b1v = bias[n+1];
            #pragma unroll
            for (int half = 0; half < 2; half++) {
                const int m = m_base + mt*16 + (lane >> 2) + half*8;
                float y0 = acc[mt][nt][half*2+0]*INV32 + b0v;
                float y1 = acc[mt][nt][half*2+1]*INV32 + b1v;
                if (ep <= 1) { y0 = phi_fn(y0); y1 = phi_fn(y1); }
                if (ep <= 2) {
                    const int h = n >> 6, d = n & 63;
                    const int b = m >> 11, t = m & (TSEQ-1);
                    const size_t off = ((size_t)((b*N_HEADS + h)*TSEQ + t))*DK + d;
                    __half* dst = (ep == 0) ? g_qf : (ep == 1) ? g_kf : g_vf;
                    *(__half2*)(dst + off) = __floats2half2_rn(y0, y1);
                } else {
                    *(float2*)(outp + (size_t)m*D_MODEL + n) = make_float2(y0, y1);
                }
            }
        }
    }
}

__global__ __launch_bounds__(256, 2) void gemm_qkv(
    const float* __restrict__ bq, const float* __restrict__ bk,
    const float* __restrict__ bv)
{
    extern __shared__ char smem[];
    const int ep = blockIdx.z;
    const float* bias = (ep == 0) ? bq : (ep == 1) ? bk : bv;
    gemm_body(ep, g_xh, bias, nullptr, smem);
}
__global__ __launch_bounds__(256, 2) void gemm_wo(
    const float* __restrict__ bo, float* __restrict__ outp)
{
    extern __shared__ char smem[];
    gemm_body(3, g_ah, bo, outp, smem);
}

// ================= attention on tensor cores (fp16) =================
#define APITCH 144
#define ATILE (128*APITCH)
#define KVTILE (DK*APITCH)

// ---------------- per-chunk K^T V and k-sum ----------------
#define CKV_SMEM (2*ATILE)          /* K, V = 36864 */
__global__ __launch_bounds__(128, 4) void chunk_kv_mma()
{
    extern __shared__ char smem[];
    const uint32_t sb = smem_to_u32(smem);
    const uint32_t SK = 0, SV = ATILE;
    const int blk = blockIdx.x;
    const int bh = blk >> 4, c = blk & 15;
    const int tid = threadIdx.x;
    const int lane = tid & 31, wid = tid >> 5;
    const size_t gbase = (size_t)bh*TSEQ*DK + (size_t)c*CHUNK*DK;

    #pragma unroll
    for (int it = 0; it < 8; it++) {
        int idx = tid + it*128;
        int r = idx >> 3, cc = idx & 7;
        const size_t so = gbase + (size_t)r*DK + cc*8;
        *(float4*)(smem + SK + r*APITCH + cc*16) = *(const float4*)(g_kf + so);
        *(float4*)(smem + SV + r*APITCH + cc*16) = *(const float4*)(g_vf + so);
    }
    {
        int r = tid;
        *(float4*)(smem + SV + r*APITCH + 128) =
            make_float4(__uint_as_float(0x00003C00u), 0.f, 0.f, 0.f);
    }
    __syncthreads();

    float f[8][4];
    #pragma unroll
    for (int n = 0; n < 8; n++)
        #pragma unroll
        for (int l = 0; l < 4; l++) f[n][l] = 0.f;
    float f8[4] = {0.f, 0.f, 0.f, 0.f};

    const uint32_t ka_rel = (uint32_t)(( ((lane>>4)&1)*8 + (lane&7) )*APITCH
                                       + (wid*16 + ((lane>>3)&1)*8)*2);
    const uint32_t vb_rel = (uint32_t)(( ((lane>>3)&1)*8 + (lane&7) )*APITCH
                                       + ((lane>>4)*8)*2);
    const uint32_t v2_rel = (uint32_t)(( ((lane>>3)&1)*8 + (lane&7) )*APITCH + 64*2);
    #pragma unroll
    for (int ks = 0; ks < 8; ks++) {
        const uint32_t krow = (uint32_t)(ks*16)*APITCH;
        uint32_t kah[4], vb[4][4], v2[2];
        ldsm4t(kah, sb + SK + krow + ka_rel);
        #pragma unroll
        for (int p = 0; p < 4; p++)
            ldsm4t(vb[p], sb + SV + krow + vb_rel + (uint32_t)(p*16*2));
        ldsm2t(v2, sb + SV + krow + v2_rel);
        #pragma unroll
        for (int nt = 0; nt < 8; nt++)
            mma16816h(f[nt], kah, &vb[nt>>1][(nt&1)*2]);
        mma16816h(f8, kah, v2);
    }

    float* kvout = g_kv + (size_t)blk*DK*DK;
    const int d0 = wid*16 + (lane>>2);
    #pragma unroll
    for (int nt = 0; nt < 8; nt++) {
        const int e = nt*8 + (lane&3)*2;
        *(float2*)(kvout + (size_t)d0*DK + e)     = make_float2(f[nt][0], f[nt][1]);
        *(float2*)(kvout + (size_t)(d0+8)*DK + e) = make_float2(f[nt][2], f[nt][3]);
    }
    if ((lane & 3) == 0) {
        g_ksum[(size_t)blk*DK + d0]     = f8[0];
        g_ksum[(size_t)blk*DK + d0 + 8] = f8[2];
    }
}

// ---------------- exclusive prefix scan: e-pair per thread, half2 stores ----------------
__global__ __launch_bounds__(256) void chunk_scan_kernel()
{
    const int bh = blockIdx.x;
    const int pidx = blockIdx.y * 256 + threadIdx.x;   // pair index
    if (pidx >= DK*KVE/2) return;
    const int pos = pidx * 2;                          // even e
    const int d = pos / KVE, e = pos % KVE;

    // independent float2 preloads (MLP=16)
    float v0[NCHUNK], v1[NCHUNK];
    #pragma unroll
    for (int c = 0; c < NCHUNK; c++) {
        const size_t blk = (size_t)(bh*NCHUNK + c);
        float a = 0.f, b = 0.f;
        if (e + 1 < DK) {
            float2 w = *(const float2*)(g_kv + blk*DK*DK + (size_t)d*DK + e);
            a = w.x; b = w.y;
        } else if (e == DK) {
            a = g_ksum[blk*DK + d];   // b stays 0 (pad col 65)
        }
        v0[c] = a; v1[c] = b;
    }
    // register-resident exclusive prefix + half2 stores
    float r0 = 0.f, r1 = 0.f;
    #pragma unroll
    for (int c = 0; c < NCHUNK; c++) {
        const size_t blk = (size_t)(bh*NCHUNK + c);
        *(__half2*)(g_kvf + blk*DK*KVE + pos) = __floats2half2_rn(r0, r1);
        r0 += v0[c]; r1 += v1[c];
    }
}

// ---------------- per-chunk attention (fp16, causal) ----------------
#define ATT_SMEM (3*ATILE + KVTILE)   /* 64512 -> 2 CTAs/SM */
__global__ __launch_bounds__(256, 2) void attn_mma_kernel()
{
    extern __shared__ char smem[];
    const uint32_t sb = smem_to_u32(smem);
    const uint32_t SQ = 0, SK = ATILE, SV = 2*ATILE;
    const uint32_t SG = 3*ATILE;

    const int blk = blockIdx.x;
    const int bh = blk >> 4, c = blk & 15;
    const int tid = threadIdx.x;
    const int lane = tid & 31, wid = tid >> 5;
    const size_t gbase = (size_t)bh*TSEQ*DK + (size_t)c*CHUNK*DK;

    #pragma unroll
    for (int it = 0; it < 4; it++) {
        int idx = tid + it*256;
        int r = idx >> 3, cc = idx & 7;
        const size_t so = gbase + (size_t)r*DK + cc*8;
        const uint32_t doff = r*APITCH + cc*16;
        *(float4*)(smem + SQ + doff) = *(const float4*)(g_qf + so);
        *(float4*)(smem + SK + doff) = *(const float4*)(g_kf + so);
        *(float4*)(smem + SV + doff) = *(const float4*)(g_vf + so);
    }
    {
        const size_t kvbase = (size_t)blk*DK*KVE;
        for (int idx = tid; idx < 576; idx += 256) {
            int r = idx / 9, cc = idx % 9;
            *(float4*)(smem + SG + r*APITCH + cc*16) =
                *(const float4*)(g_kvf + kvbase + (size_t)r*KVE + cc*8);
        }
    }
    __syncthreads();

    const int rbase = wid * 16;
    const uint32_t qa_rel = (uint32_t)((rbase + (lane & 15))*APITCH + (lane >> 4)*16);
    uint32_t qa[4][4];
    #pragma unroll
    for (int ks = 0; ks < 4; ks++)
        ldsm4(qa[ks], sb + SQ + qa_rel + ks*32);

    float o[9][4];
    #pragma unroll
    for (int n = 0; n < 9; n++)
        #pragma unroll
        for (int l = 0; l < 4; l++) o[n][l] = 0.f;

    // ---- inter-chunk: o += q @ KV_prev ----
    const uint32_t gb_rel = (uint32_t)(( ((lane>>3)&1)*8 + (lane&7) )*APITCH + ((lane>>4)*8)*2);
    const uint32_t g2_rel = (uint32_t)(( ((lane>>3)&1)*8 + (lane&7) )*APITCH + 64*2);
    #pragma unroll
    for (int ks = 0; ks < 4; ks++) {
        const uint32_t krow = (uint32_t)(ks*16)*APITCH;
        uint32_t gb[4][4], g2[2];
        #pragma unroll
        for (int p = 0; p < 4; p++)
            ldsm4t(gb[p], sb + SG + krow + gb_rel + (uint32_t)(p*16*2));
        ldsm2t(g2, sb + SG + krow + g2_rel);
        #pragma unroll
        for (int nt = 0; nt < 8; nt++)
            mma16816h(o[nt], qa[ks], &gb[nt>>1][(nt&1)*2]);
        mma16816h(o[8], qa[ks], g2);
    }

    // ---- intra-chunk causal ----
    float zacc0 = 0.f, zacc1 = 0.f;
    const int row0 = rbase + (lane >> 2), row1 = row0 + 8;
    const int ncc = wid/2 + 1;
    const uint32_t kb_col = (uint32_t)(((lane>>3)&1)*16);
    const uint32_t vb_rel = (uint32_t)(( ((lane>>3)&1)*8 + (lane&7) )*APITCH + ((lane>>4)*8)*2);

    for (int cc = 0; cc < ncc; cc++) {
        const int c0 = cc*32;
        float s[4][4];
        #pragma unroll
        for (int n = 0; n < 4; n++)
            #pragma unroll
            for (int l = 0; l < 4; l++) s[n][l] = 0.f;
        #pragma unroll
        for (int ks = 0; ks < 4; ks++) {
            uint32_t kb[2][4];
            #pragma unroll
            for (int p = 0; p < 2; p++) {
                const uint32_t kbo = (uint32_t)((c0 + 16*p + ((lane>>4)<<3) + (lane&7))*APITCH)
                                     + kb_col + (uint32_t)(ks*32);
                ldsm4(kb[p], sb + SK + kbo);
            }
            #pragma unroll
            for (int nt = 0; nt < 4; nt++)
                mma16816h(s[nt], qa[ks], &kb[nt>>1][(nt&1)*2]);
        }
        uint32_t af[2][4];
        #pragma unroll
        for (int nt = 0; nt < 4; nt++) {
            const int colj = c0 + nt*8 + (lane&3)*2;
            float e0 = (colj   <= row0) ? s[nt][0] : 0.f;
            float e1 = (colj+1 <= row0) ? s[nt][1] : 0.f;
            float e2 = (colj   <= row1) ? s[nt][2] : 0.f;
            float e3 = (colj+1 <= row1) ? s[nt][3] : 0.f;
            zacc0 += e0 + e1;
            zacc1 += e2 + e3;
            const int kk = nt >> 1, half = nt & 1;
            af[kk][half*2+0] = pack_h(e0, e1);
            af[kk][half*2+1] = pack_h(e2, e3);
        }
        #pragma unroll
        for (int kk = 0; kk < 2; kk++) {
            const uint32_t krow = (uint32_t)((c0 + kk*16))*APITCH;
            uint32_t vb[4][4];
            #pragma unroll
            for (int p = 0; p < 4; p++)
                ldsm4t(vb[p], sb + SV + krow + vb_rel + (uint32_t)(p*16*2));
            #pragma unroll
            for (int nt = 0; nt < 8; nt++)
                mma16816h(o[nt], af[kk], &vb[nt>>1][(nt&1)*2]);
        }
    }

    float z0 = zacc0 + ((lane & 3) == 0 ? o[8][0] : 0.f);
    float z1 = zacc1 + ((lane & 3) == 0 ? o[8][2] : 0.f);
    z0 += __shfl_xor_sync(0xffffffff, z0, 1);
    z0 += __shfl_xor_sync(0xffffffff, z0, 2);
    z1 += __shfl_xor_sync(0xffffffff, z1, 1);
    z1 += __shfl_xor_sync(0xffffffff, z1, 2);
    const float inv0 = 1.f / (z0 + 1e-6f);
    const float inv1 = 1.f / (z1 + 1e-6f);

    const int b = bh >> 4, h = bh & 15;
    const size_t mbase0 = ((size_t)(b*TSEQ + c*CHUNK + row0))*D_MODEL + h*DK;
    const size_t mbase1 = ((size_t)(b*TSEQ + c*CHUNK + row1))*D_MODEL + h*DK;
    #pragma unroll
    for (int nt = 0; nt < 8; nt++) {
        const int e = nt*8 + (lane&3)*2;
        float y0 = o[nt][0]*inv0, y1 = o[nt][1]*inv0;
        float y2 = o[nt][2]*inv1, y3 = o[nt][3]*inv1;
        *(__half2*)(g_ah + mbase0 + e) = __floats2half2_rn(y0, y1);
        *(__half2*)(g_ah + mbase1 + e) = __floats2half2_rn(y2, y3);
    }
}

// ---------------- launch ----------------
extern "C" void kernel_launch(void* const* d_in, const int* in_sizes, int n_in,
                              void* d_out, int out_size)
{
    (void)in_sizes; (void)n_in; (void)out_size;
    const float* x  = (const float*)d_in[0];
    const float* Wq = (const float*)d_in[1];
    const float* bq = (const float*)d_in[2];
    const float* Wk = (const float*)d_in[3];
    const float* bk = (const float*)d_in[4];
    const float* Wv = (const float*)d_in[5];
    const float* bv = (const float*)d_in[6];
    const float* Wo = (const float*)d_in[7];
    const float* bo = (const float*)d_in[8];
    float* out = (float*)d_out;

    cudaFuncSetAttribute(gemm_qkv, cudaFuncAttributeMaxDynamicSharedMemorySize, GEMM_SMEM);
    cudaFuncSetAttribute(gemm_wo,  cudaFuncAttributeMaxDynamicSharedMemorySize, GEMM_SMEM);
    cudaFuncSetAttribute(chunk_kv_mma,    cudaFuncAttributeMaxDynamicSharedMemorySize, CKV_SMEM);
    cudaFuncSetAttribute(attn_mma_kernel, cudaFuncAttributeMaxDynamicSharedMemorySize, ATT_SMEM);

    split_all_kernel<<<8192, 256>>>(x, Wq, Wk, Wv, Wo);

    dim3 gq(D_MODEL/128, MROWS/128, 3);   // (8, 32, 3)
    gemm_qkv<<<gq, 256, GEMM_SMEM>>>(bq, bk, bv);

    chunk_kv_mma<<<NBH*NCHUNK, 128, CKV_SMEM>>>();
    dim3 gs(NBH, (DK*KVE/2 + 255)/256);   // (32, 9)
    chunk_scan_kernel<<<gs, 256>>>();
    attn_mma_kernel<<<NBH*NCHUNK, 256, ATT_SMEM>>>();

    dim3 go(D_MODEL/128, MROWS/128);      // (8, 32)
    gemm_wo<<<go, 256, GEMM_SMEM>>>(bo, out);
}

// round 16
// speedup vs baseline: 1.0041x; 1.0041x over previous
#include <cuda_runtime.h>
#include <cuda_bf16.h>
#include <cuda_fp16.h>
#include <cstdint>

#define D_MODEL 1024
#define N_HEADS 16
#define DK 64
#define BATCH 2
#define TSEQ 2048
#define MROWS (BATCH*TSEQ)   /* 4096 */
#define CHUNK 128
#define NCHUNK (TSEQ/CHUNK)  /* 16 */
#define NBH (BATCH*N_HEADS)  /* 32 */
#define KVE 72               /* KV ext cols: 64 + ksum + pad */

// ---------------- scratch (static device arrays; no allocation) ----------------
__device__ float g_kv[NBH*NCHUNK*DK*DK];
__device__ float g_ksum[NBH*NCHUNK*DK];
// fp16 GEMM operands (W pre-scaled by 32)
__device__ __half g_xh[MROWS*D_MODEL];
__device__ __half g_wh[4*D_MODEL*D_MODEL];
__device__ __half g_ah[MROWS*D_MODEL];
// fp16 attention operands (all single fp16)
__device__ __half g_qf[NBH*TSEQ*DK];
__device__ __half g_kf[NBH*TSEQ*DK];
__device__ __half g_vf[NBH*TSEQ*DK];
__device__ __half g_kvf[NBH*NCHUNK*DK*KVE];

__device__ __forceinline__ float phi_fn(float x) {
    return x > 0.f ? x + 1.f : __expf(x);
}
__device__ __forceinline__ uint32_t smem_to_u32(const void* smem_ptr) {
    uint32_t addr;
    asm("{ .reg .u64 tmp; cvta.to.shared.u64 tmp, %1; cvt.u32.u64 %0, tmp; }"
        : "=r"(addr) : "l"(smem_ptr));
    return addr;
}

// ---------------- mma / ldmatrix / cp.async primitives ----------------
__device__ __forceinline__ void mma16816h(float* d, const uint32_t* a, const uint32_t* b) {
    asm volatile(
        "mma.sync.aligned.m16n8k16.row.col.f32.f16.f16.f32 "
        "{%0,%1,%2,%3}, {%4,%5,%6,%7}, {%8,%9}, {%0,%1,%2,%3};"
        : "+f"(d[0]), "+f"(d[1]), "+f"(d[2]), "+f"(d[3])
        : "r"(a[0]), "r"(a[1]), "r"(a[2]), "r"(a[3]), "r"(b[0]), "r"(b[1]));
}
__device__ __forceinline__ void ldsm4(uint32_t* r, uint32_t addr) {
    asm volatile("ldmatrix.sync.aligned.m8n8.x4.shared.b16 {%0,%1,%2,%3}, [%4];"
        : "=r"(r[0]), "=r"(r[1]), "=r"(r[2]), "=r"(r[3]) : "r"(addr));
}
__device__ __forceinline__ void ldsm4t(uint32_t* r, uint32_t addr) {
    asm volatile("ldmatrix.sync.aligned.m8n8.x4.trans.shared.b16 {%0,%1,%2,%3}, [%4];"
        : "=r"(r[0]), "=r"(r[1]), "=r"(r[2]), "=r"(r[3]) : "r"(addr));
}
__device__ __forceinline__ void ldsm2t(uint32_t* r, uint32_t addr) {
    asm volatile("ldmatrix.sync.aligned.m8n8.x2.trans.shared.b16 {%0,%1}, [%2];"
        : "=r"(r[0]), "=r"(r[1]) : "r"(addr));
}
#define CP_ASYNC16(dst, src) \
    asm volatile("cp.async.cg.shared.global [%0], [%1], 16;" :: "r"(dst), "l"(src))
#define CP_COMMIT() asm volatile("cp.async.commit_group;" ::: "memory")
#define CP_WAIT1()  asm volatile("cp.async.wait_group 1;" ::: "memory")
#define CP_WAIT0()  asm volatile("cp.async.wait_group 0;" ::: "memory")

__device__ __forceinline__ uint32_t pack_h(float a, float b) {
    __half2 p = __floats2half2_rn(a, b);
    return *reinterpret_cast<uint32_t*>(&p);
}
#define SWZ128(off) ((uint32_t)(off) ^ ((((uint32_t)(off)) >> 3) & 0x70))

// ---------------- merged input conversion ----------------
__global__ __launch_bounds__(256) void split_all_kernel(
    const float* __restrict__ x,
    const float* __restrict__ w0, const float* __restrict__ w1,
    const float* __restrict__ w2, const float* __restrict__ w3)
{
    const int per = D_MODEL*D_MODEL/4;          // 262144
    int i = blockIdx.x * 256 + threadIdx.x;
    if (i < MROWS*D_MODEL/4) {
        float4 v = ((const float4*)x)[i];
        ((__half2*)(g_xh + 4*(size_t)i))[0] = __floats2half2_rn(v.x, v.y);
        ((__half2*)(g_xh + 4*(size_t)i))[1] = __floats2half2_rn(v.z, v.w);
    } else {
        int j = i - MROWS*D_MODEL/4;
        int sel = j >> 18, loc = j & (per - 1);
        const float* src = (sel == 0) ? w0 : (sel == 1) ? w1 : (sel == 2) ? w2 : w3;
        float4 v = ((const float4*)src)[loc];
        size_t o = (size_t)sel * D_MODEL * D_MODEL + 4*(size_t)loc;
        ((__half2*)(g_wh + o))[0] = __floats2half2_rn(v.x*32.f, v.y*32.f);
        ((__half2*)(g_wh + o))[1] = __floats2half2_rn(v.z*32.f, v.w*32.f);
    }
}

// ---------------- fp16 GEMM: BK=64, 3-stage, SW128, 2 CTAs/SM ----------------
#define TILE_B (128*128)
#define STAGE_B (2*TILE_B)
#define GEMM_SMEM (3*STAGE_B)       /* 98304 */
#define NSTG 16

__device__ __forceinline__ void gemm_body(
    int ep, const __half* __restrict__ Xh,
    const float* __restrict__ bias, float* __restrict__ outp, char* smem)
{
    const uint32_t sb = smem_to_u32(smem);
    const int tid = threadIdx.x;
    const int lane = tid & 31, wid = tid >> 5;
    const int wm = wid & 1, wn = wid >> 1;
    const int m0 = blockIdx.y * 128;
    const int n0 = blockIdx.x * 128;

    const __half* Wh = g_wh + (size_t)ep * D_MODEL * D_MODEL;

    float acc[4][4][4];
    #pragma unroll
    for (int i = 0; i < 4; i++)
        #pragma unroll
        for (int j = 0; j < 4; j++)
            #pragma unroll
            for (int l = 0; l < 4; l++) acc[i][j][l] = 0.f;

    const int lr = tid >> 2, lu = (tid & 3) * 2;
    const uint32_t d00 = SWZ128(lr*128 + lu*16),        d01 = SWZ128(lr*128 + (lu+1)*16);
    const uint32_t d10 = SWZ128((lr+64)*128 + lu*16),   d11 = SWZ128((lr+64)*128 + (lu+1)*16);

    auto load_stage = [&](int buf, int k0) {
        uint32_t base = sb + buf * STAGE_B;
        CP_ASYNC16(base + d00, Xh + (size_t)(m0 + lr)*D_MODEL + k0 + lu*8);
        CP_ASYNC16(base + d01, Xh + (size_t)(m0 + lr)*D_MODEL + k0 + lu*8 + 8);
        CP_ASYNC16(base + d10, Xh + (size_t)(m0 + lr + 64)*D_MODEL + k0 + lu*8);
        CP_ASYNC16(base + d11, Xh + (size_t)(m0 + lr + 64)*D_MODEL + k0 + lu*8 + 8);
        base += TILE_B;
        CP_ASYNC16(base + d00, Wh + (size_t)(n0 + lr)*D_MODEL + k0 + lu*8);
        CP_ASYNC16(base + d01, Wh + (size_t)(n0 + lr)*D_MODEL + k0 + lu*8 + 8);
        CP_ASYNC16(base + d10, Wh + (size_t)(n0 + lr + 64)*D_MODEL + k0 + lu*8);
        CP_ASYNC16(base + d11, Wh + (size_t)(n0 + lr + 64)*D_MODEL + k0 + lu*8 + 8);
        CP_COMMIT();
    };

    load_stage(0, 0);
    load_stage(1, 64);

    for (int kc = 0; kc < NSTG; kc++) {
        if (kc < NSTG-1) { CP_WAIT1(); } else { CP_WAIT0(); }
        __syncthreads();
        if (kc + 2 < NSTG) load_stage((kc + 2) % 3, (kc + 2) * 64);

        const uint32_t base = sb + (kc % 3) * STAGE_B;
        #pragma unroll
        for (int ks = 0; ks < 4; ks++) {
            uint32_t ah[4][4], bh[2][4];
            #pragma unroll
            for (int mt = 0; mt < 4; mt++) {
                const int rA = wm*64 + mt*16 + (lane & 15);
                const uint32_t offA = SWZ128(rA*128 + ((lane >> 4) + 2*ks)*16);
                ldsm4(ah[mt], base + offA);
            }
            #pragma unroll
            for (int op = 0; op < 2; op++) {
                const int rB = wn*32 + op*16 + ((lane >> 4) << 3) + (lane & 7);
                const uint32_t offB = SWZ128(rB*128 + (((lane >> 3) & 1) + 2*ks)*16);
                ldsm4(bh[op], base + TILE_B + offB);
            }
            #pragma unroll
            for (int mt = 0; mt < 4; mt++)
                #pragma unroll
                for (int nt = 0; nt < 4; nt++) {
                    const uint32_t* bhp = &bh[nt >> 1][(nt & 1) * 2];
                    mma16816h(acc[mt][nt], ah[mt], bhp);
                }
        }
    }
    __syncthreads();

    // ---- epilogue (acc is 32x scaled) ----
    const float INV32 = 1.f/32.f;
    const int m_base = m0 + wm*64;
    #pragma unroll
    for (int mt = 0; mt < 4; mt++) {
        #pragma unroll
        for (int nt = 0; nt < 4; nt++) {
            const int n = n0 + wn*32 + nt*8 + (lane & 3)*2;
            const float b0v = bias[n], b1v = bias[n+1];
            #pragma unroll
            for (int half = 0; half < 2; half++) {
                const int m = m_base + mt*16 + (lane >> 2) + half*8;
                float y0 = acc[mt][nt][half*2+0]*INV32 + b0v;
                float y1 = acc[mt][nt][half*2+1]*INV32 + b1v;
                if (ep <= 1) { y0 = phi_fn(y0); y1 = phi_fn(y1); }
                if (ep <= 2) {
                    const int h = n >> 6, d = n & 63;
                    const int b = m >> 11, t = m & (TSEQ-1);
                    const size_t off = ((size_t)((b*N_HEADS + h)*TSEQ + t))*DK + d;
                    __half* dst = (ep == 0) ? g_qf : (ep == 1) ? g_kf : g_vf;
                    *(__half2*)(dst + off) = __floats2half2_rn(y0, y1);
                } else {
                    *(float2*)(outp + (size_t)m*D_MODEL + n) = make_float2(y0, y1);
                }
            }
        }
    }
}

__global__ __launch_bounds__(256, 2) void gemm_qkv(
    const float* __restrict__ bq, const float* __restrict__ bk,
    const float* __restrict__ bv)
{
    extern __shared__ char smem[];
    const int ep = blockIdx.z;
    const float* bias = (ep == 0) ? bq : (ep == 1) ? bk : bv;
    gemm_body(ep, g_xh, bias, nullptr, smem);
}
__global__ __launch_bounds__(256, 2) void gemm_wo(
    const float* __restrict__ bo, float* __restrict__ outp)
{
    extern __shared__ char smem[];
    gemm_body(3, g_ah, bo, outp, smem);
}

// ================= attention on tensor cores (fp16) =================
#define APITCH 144
#define ATILE (128*APITCH)
#define KVTILE (DK*APITCH)

// ---------------- per-chunk K^T V and k-sum ----------------
#define CKV_SMEM (2*ATILE)          /* K, V = 36864 */
__global__ __launch_bounds__(128, 4) void chunk_kv_mma()
{
    extern __shared__ char smem[];
    const uint32_t sb = smem_to_u32(smem);
    const uint32_t SK = 0, SV = ATILE;
    const int blk = blockIdx.x;
    const int bh = blk >> 4, c = blk & 15;
    const int tid = threadIdx.x;
    const int lane = tid & 31, wid = tid >> 5;
    const size_t gbase = (size_t)bh*TSEQ*DK + (size_t)c*CHUNK*DK;

    #pragma unroll
    for (int it = 0; it < 8; it++) {
        int idx = tid + it*128;
        int r = idx >> 3, cc = idx & 7;
        const size_t so = gbase + (size_t)r*DK + cc*8;
        *(float4*)(smem + SK + r*APITCH + cc*16) = *(const float4*)(g_kf + so);
        *(float4*)(smem + SV + r*APITCH + cc*16) = *(const float4*)(g_vf + so);
    }
    {
        int r = tid;
        *(float4*)(smem + SV + r*APITCH + 128) =
            make_float4(__uint_as_float(0x00003C00u), 0.f, 0.f, 0.f);
    }
    __syncthreads();

    float f[8][4];
    #pragma unroll
    for (int n = 0; n < 8; n++)
        #pragma unroll
        for (int l = 0; l < 4; l++) f[n][l] = 0.f;
    float f8[4] = {0.f, 0.f, 0.f, 0.f};

    const uint32_t ka_rel = (uint32_t)(( ((lane>>4)&1)*8 + (lane&7) )*APITCH
                                       + (wid*16 + ((lane>>3)&1)*8)*2);
    const uint32_t vb_rel = (uint32_t)(( ((lane>>3)&1)*8 + (lane&7) )*APITCH
                                       + ((lane>>4)*8)*2);
    const uint32_t v2_rel = (uint32_t)(( ((lane>>3)&1)*8 + (lane&7) )*APITCH + 64*2);
    #pragma unroll
    for (int ks = 0; ks < 8; ks++) {
        const uint32_t krow = (uint32_t)(ks*16)*APITCH;
        uint32_t kah[4], vb[4][4], v2[2];
        ldsm4t(kah, sb + SK + krow + ka_rel);
        #pragma unroll
        for (int p = 0; p < 4; p++)
            ldsm4t(vb[p], sb + SV + krow + vb_rel + (uint32_t)(p*16*2));
        ldsm2t(v2, sb + SV + krow + v2_rel);
        #pragma unroll
        for (int nt = 0; nt < 8; nt++)
            mma16816h(f[nt], kah, &vb[nt>>1][(nt&1)*2]);
        mma16816h(f8, kah, v2);
    }

    float* kvout = g_kv + (size_t)blk*DK*DK;
    const int d0 = wid*16 + (lane>>2);
    #pragma unroll
    for (int nt = 0; nt < 8; nt++) {
        const int e = nt*8 + (lane&3)*2;
        *(float2*)(kvout + (size_t)d0*DK + e)     = make_float2(f[nt][0], f[nt][1]);
        *(float2*)(kvout + (size_t)(d0+8)*DK + e) = make_float2(f[nt][2], f[nt][3]);
    }
    if ((lane & 3) == 0) {
        g_ksum[(size_t)blk*DK + d0]     = f8[0];
        g_ksum[(size_t)blk*DK + d0 + 8] = f8[2];
    }
}

// ---------------- exclusive prefix scan: preload all chunks, then scan ----------------
__global__ __launch_bounds__(256) void chunk_scan_kernel()
{
    const int bh = blockIdx.x;
    const int pos = blockIdx.y * 256 + threadIdx.x;
    if (pos >= DK*KVE) return;
    const int d = pos / KVE, e = pos % KVE;

    float vals[NCHUNK];
    #pragma unroll
    for (int c = 0; c < NCHUNK; c++) {
        const size_t blk = (size_t)(bh*NCHUNK + c);
        float v = 0.f;
        if (e < DK)       v = g_kv[blk*DK*DK + (size_t)d*DK + e];
        else if (e == DK) v = g_ksum[blk*DK + d];
        vals[c] = v;
    }
    float run = 0.f;
    #pragma unroll
    for (int c = 0; c < NCHUNK; c++) {
        const size_t blk = (size_t)(bh*NCHUNK + c);
        g_kvf[blk*DK*KVE + pos] = __float2half(run);
        run += vals[c];
    }
}

// ---------------- per-chunk attention (fp16, causal) ----------------
#define ATT_SMEM (3*ATILE + KVTILE)   /* 64512 -> 2 CTAs/SM */
__global__ __launch_bounds__(256, 2) void attn_mma_kernel()
{
    extern __shared__ char smem[];
    const uint32_t sb = smem_to_u32(smem);
    const uint32_t SQ = 0, SK = ATILE, SV = 2*ATILE;
    const uint32_t SG = 3*ATILE;

    const int blk = blockIdx.x;
    const int bh = blk >> 4, c = blk & 15;
    const int tid = threadIdx.x;
    const int lane = tid & 31, wid = tid >> 5;
    const size_t gbase = (size_t)bh*TSEQ*DK + (size_t)c*CHUNK*DK;

    #pragma unroll
    for (int it = 0; it < 4; it++) {
        int idx = tid + it*256;
        int r = idx >> 3, cc = idx & 7;
        const size_t so = gbase + (size_t)r*DK + cc*8;
        const uint32_t doff = r*APITCH + cc*16;
        *(float4*)(smem + SQ + doff) = *(const float4*)(g_qf + so);
        *(float4*)(smem + SK + doff) = *(const float4*)(g_kf + so);
        *(float4*)(smem + SV + doff) = *(const float4*)(g_vf + so);
    }
    if (c > 0) {
        const size_t kvbase = (size_t)blk*DK*KVE;
        for (int idx = tid; idx < 576; idx += 256) {
            int r = idx / 9, cc = idx % 9;
            *(float4*)(smem + SG + r*APITCH + cc*16) =
                *(const float4*)(g_kvf + kvbase + (size_t)r*KVE + cc*8);
        }
    }
    __syncthreads();

    // SMSP-balanced row-group map: strips per group g = g/2+1; pair {w, 11-w}
    const int rgrp = (wid < 4) ? wid : 11 - wid;
    const int rbase = rgrp * 16;
    const uint32_t qa_rel = (uint32_t)((rbase + (lane & 15))*APITCH + (lane >> 4)*16);
    uint32_t qa[4][4];
    #pragma unroll
    for (int ks = 0; ks < 4; ks++)
        ldsm4(qa[ks], sb + SQ + qa_rel + ks*32);

    float o[9][4];
    #pragma unroll
    for (int n = 0; n < 9; n++)
        #pragma unroll
        for (int l = 0; l < 4; l++) o[n][l] = 0.f;

    // ---- inter-chunk: o += q @ KV_prev (skip for c==0: prefix is exactly zero) ----
    if (c > 0) {
        const uint32_t gb_rel = (uint32_t)(( ((lane>>3)&1)*8 + (lane&7) )*APITCH + ((lane>>4)*8)*2);
        const uint32_t g2_rel = (uint32_t)(( ((lane>>3)&1)*8 + (lane&7) )*APITCH + 64*2);
        #pragma unroll
        for (int ks = 0; ks < 4; ks++) {
            const uint32_t krow = (uint32_t)(ks*16)*APITCH;
            uint32_t gb[4][4], g2[2];
            #pragma unroll
            for (int p = 0; p < 4; p++)
                ldsm4t(gb[p], sb + SG + krow + gb_rel + (uint32_t)(p*16*2));
            ldsm2t(g2, sb + SG + krow + g2_rel);
            #pragma unroll
            for (int nt = 0; nt < 8; nt++)
                mma16816h(o[nt], qa[ks], &gb[nt>>1][(nt&1)*2]);
            mma16816h(o[8], qa[ks], g2);
        }
    }

    // ---- intra-chunk causal ----
    float zacc0 = 0.f, zacc1 = 0.f;
    const int row0 = rbase + (lane >> 2), row1 = row0 + 8;
    const int ncc = rgrp/2 + 1;
    const uint32_t kb_col = (uint32_t)(((lane>>3)&1)*16);
    const uint32_t vb_rel = (uint32_t)(( ((lane>>3)&1)*8 + (lane&7) )*APITCH + ((lane>>4)*8)*2);

    for (int cc = 0; cc < ncc; cc++) {
        const int c0 = cc*32;
        float s[4][4];
        #pragma unroll
        for (int n = 0; n < 4; n++)
            #pragma unroll
            for (int l = 0; l < 4; l++) s[n][l] = 0.f;
        #pragma unroll
        for (int ks = 0; ks < 4; ks++) {
            uint32_t kb[2][4];
            #pragma unroll
            for (int p = 0; p < 2; p++) {
                const uint32_t kbo = (uint32_t)((c0 + 16*p + ((lane>>4)<<3) + (lane&7))*APITCH)
                                     + kb_col + (uint32_t)(ks*32);
                ldsm4(kb[p], sb + SK + kbo);
            }
            #pragma unroll
            for (int nt = 0; nt < 4; nt++)
                mma16816h(s[nt], qa[ks], &kb[nt>>1][(nt&1)*2]);
        }
        uint32_t af[2][4];
        #pragma unroll
        for (int nt = 0; nt < 4; nt++) {
            const int colj = c0 + nt*8 + (lane&3)*2;
            float e0 = (colj   <= row0) ? s[nt][0] : 0.f;
            float e1 = (colj+1 <= row0) ? s[nt][1] : 0.f;
            float e2 = (colj   <= row1) ? s[nt][2] : 0.f;
            float e3 = (colj+1 <= row1) ? s[nt][3] : 0.f;
            zacc0 += e0 + e1;
            zacc1 += e2 + e3;
            const int kk = nt >> 1, half = nt & 1;
            af[kk][half*2+0] = pack_h(e0, e1);
            af[kk][half*2+1] = pack_h(e2, e3);
        }
        #pragma unroll
        for (int kk = 0; kk < 2; kk++) {
            const uint32_t krow = (uint32_t)((c0 + kk*16))*APITCH;
            uint32_t vb[4][4];
            #pragma unroll
            for (int p = 0; p < 4; p++)
                ldsm4t(vb[p], sb + SV + krow + vb_rel + (uint32_t)(p*16*2));
            #pragma unroll
            for (int nt = 0; nt < 8; nt++)
                mma16816h(o[nt], af[kk], &vb[nt>>1][(nt&1)*2]);
        }
    }

    float z0 = zacc0 + ((lane & 3) == 0 ? o[8][0] : 0.f);
    float z1 = zacc1 + ((lane & 3) == 0 ? o[8][2] : 0.f);
    z0 += __shfl_xor_sync(0xffffffff, z0, 1);
    z0 += __shfl_xor_sync(0xffffffff, z0, 2);
    z1 += __shfl_xor_sync(0xffffffff, z1, 1);
    z1 += __shfl_xor_sync(0xffffffff, z1, 2);
    const float inv0 = 1.f / (z0 + 1e-6f);
    const float inv1 = 1.f / (z1 + 1e-6f);

    const int b = bh >> 4, h = bh & 15;
    const size_t mbase0 = ((size_t)(b*TSEQ + c*CHUNK + row0))*D_MODEL + h*DK;
    const size_t mbase1 = ((size_t)(b*TSEQ + c*CHUNK + row1))*D_MODEL + h*DK;
    #pragma unroll
    for (int nt = 0; nt < 8; nt++) {
        const int e = nt*8 + (lane&3)*2;
        float y0 = o[nt][0]*inv0, y1 = o[nt][1]*inv0;
        float y2 = o[nt][2]*inv1, y3 = o[nt][3]*inv1;
        *(__half2*)(g_ah + mbase0 + e) = __floats2half2_rn(y0, y1);
        *(__half2*)(g_ah + mbase1 + e) = __floats2half2_rn(y2, y3);
    }
}

// ---------------- launch ----------------
extern "C" void kernel_launch(void* const* d_in, const int* in_sizes, int n_in,
                              void* d_out, int out_size)
{
    (void)in_sizes; (void)n_in; (void)out_size;
    const float* x  = (const float*)d_in[0];
    const float* Wq = (const float*)d_in[1];
    const float* bq = (const float*)d_in[2];
    const float* Wk = (const float*)d_in[3];
    const float* bk = (const float*)d_in[4];
    const float* Wv = (const float*)d_in[5];
    const float* bv = (const float*)d_in[6];
    const float* Wo = (const float*)d_in[7];
    const float* bo = (const float*)d_in[8];
    float* out = (float*)d_out;

    cudaFuncSetAttribute(gemm_qkv, cudaFuncAttributeMaxDynamicSharedMemorySize, GEMM_SMEM);
    cudaFuncSetAttribute(gemm_wo,  cudaFuncAttributeMaxDynamicSharedMemorySize, GEMM_SMEM);
    cudaFuncSetAttribute(chunk_kv_mma,    cudaFuncAttributeMaxDynamicSharedMemorySize, CKV_SMEM);
    cudaFuncSetAttribute(attn_mma_kernel, cudaFuncAttributeMaxDynamicSharedMemorySize, ATT_SMEM);

    split_all_kernel<<<8192, 256>>>(x, Wq, Wk, Wv, Wo);

    dim3 gq(D_MODEL/128, MROWS/128, 3);   // (8, 32, 3)
    gemm_qkv<<<gq, 256, GEMM_SMEM>>>(bq, bk, bv);

    chunk_kv_mma<<<NBH*NCHUNK, 128, CKV_SMEM>>>();
    dim3 gs(NBH, (DK*KVE + 255)/256);     // (32, 18)
    chunk_scan_kernel<<<gs, 256>>>();
    attn_mma_kernel<<<NBH*NCHUNK, 256, ATT_SMEM>>>();

    dim3 go(D_MODEL/128, MROWS/128);      // (8, 32)
    gemm_wo<<<go, 256, GEMM_SMEM>>>(bo, out);
}

// round 17
// speedup vs baseline: 1.0303x; 1.0261x over previous
#include <cuda_runtime.h>
#include <cuda_bf16.h>
#include <cuda_fp16.h>
#include <cstdint>

#define D_MODEL 1024
#define N_HEADS 16
#define DK 64
#define BATCH 2
#define TSEQ 2048
#define MROWS (BATCH*TSEQ)   /* 4096 */
#define CHUNK 128
#define NCHUNK (TSEQ/CHUNK)  /* 16 */
#define NBH (BATCH*N_HEADS)  /* 32 */
#define KVE 72               /* KV ext cols: 64 + ksum + pad */

// ---------------- scratch (static device arrays; no allocation) ----------------
__device__ float g_kv[NBH*NCHUNK*DK*DK];
__device__ float g_ksum[NBH*NCHUNK*DK];
__device__ __half g_xh[MROWS*D_MODEL];
__device__ __half g_wh[4*D_MODEL*D_MODEL];
__device__ __half g_ah[MROWS*D_MODEL];
__device__ __half g_qf[NBH*TSEQ*DK];
__device__ __half g_kf[NBH*TSEQ*DK];
__device__ __half g_vf[NBH*TSEQ*DK];
__device__ __half g_kvf[NBH*NCHUNK*DK*KVE];

__device__ __forceinline__ float phi_fn(float x) {
    return x > 0.f ? x + 1.f : __expf(x);
}
__device__ __forceinline__ uint32_t smem_to_u32(const void* smem_ptr) {
    uint32_t addr;
    asm("{ .reg .u64 tmp; cvta.to.shared.u64 tmp, %1; cvt.u32.u64 %0, tmp; }"
        : "=r"(addr) : "l"(smem_ptr));
    return addr;
}

// ---------------- PDL primitives (sm_90+ base ISA) ----------------
#define GDC_WAIT()   asm volatile("griddepcontrol.wait;" ::: "memory")
#define GDC_LAUNCH() asm volatile("griddepcontrol.launch_dependents;" ::: "memory")

// ---------------- mma / ldmatrix / cp.async primitives ----------------
__device__ __forceinline__ void mma16816h(float* d, const uint32_t* a, const uint32_t* b) {
    asm volatile(
        "mma.sync.aligned.m16n8k16.row.col.f32.f16.f16.f32 "
        "{%0,%1,%2,%3}, {%4,%5,%6,%7}, {%8,%9}, {%0,%1,%2,%3};"
        : "+f"(d[0]), "+f"(d[1]), "+f"(d[2]), "+f"(d[3])
        : "r"(a[0]), "r"(a[1]), "r"(a[2]), "r"(a[3]), "r"(b[0]), "r"(b[1]));
}
__device__ __forceinline__ void ldsm4(uint32_t* r, uint32_t addr) {
    asm volatile("ldmatrix.sync.aligned.m8n8.x4.shared.b16 {%0,%1,%2,%3}, [%4];"
        : "=r"(r[0]), "=r"(r[1]), "=r"(r[2]), "=r"(r[3]) : "r"(addr));
}
__device__ __forceinline__ void ldsm4t(uint32_t* r, uint32_t addr) {
    asm volatile("ldmatrix.sync.aligned.m8n8.x4.trans.shared.b16 {%0,%1,%2,%3}, [%4];"
        : "=r"(r[0]), "=r"(r[1]), "=r"(r[2]), "=r"(r[3]) : "r"(addr));
}
__device__ __forceinline__ void ldsm2t(uint32_t* r, uint32_t addr) {
    asm volatile("ldmatrix.sync.aligned.m8n8.x2.trans.shared.b16 {%0,%1}, [%2];"
        : "=r"(r[0]), "=r"(r[1]) : "r"(addr));
}
#define CP_ASYNC16(dst, src) \
    asm volatile("cp.async.cg.shared.global [%0], [%1], 16;" :: "r"(dst), "l"(src))
#define CP_COMMIT() asm volatile("cp.async.commit_group;" ::: "memory")
#define CP_WAIT1()  asm volatile("cp.async.wait_group 1;" ::: "memory")
#define CP_WAIT0()  asm volatile("cp.async.wait_group 0;" ::: "memory")

__device__ __forceinline__ uint32_t pack_h(float a, float b) {
    __half2 p = __floats2half2_rn(a, b);
    return *reinterpret_cast<uint32_t*>(&p);
}
#define SWZ128(off) ((uint32_t)(off) ^ ((((uint32_t)(off)) >> 3) & 0x70))

// ---------------- merged input conversion ----------------
__global__ __launch_bounds__(256) void split_all_kernel(
    const float* __restrict__ x,
    const float* __restrict__ w0, const float* __restrict__ w1,
    const float* __restrict__ w2, const float* __restrict__ w3)
{
    const int per = D_MODEL*D_MODEL/4;          // 262144
    int i = blockIdx.x * 256 + threadIdx.x;
    if (i < MROWS*D_MODEL/4) {
        float4 v = ((const float4*)x)[i];
        ((__half2*)(g_xh + 4*(size_t)i))[0] = __floats2half2_rn(v.x, v.y);
        ((__half2*)(g_xh + 4*(size_t)i))[1] = __floats2half2_rn(v.z, v.w);
    } else {
        int j = i - MROWS*D_MODEL/4;
        int sel = j >> 18, loc = j & (per - 1);
        const float* src = (sel == 0) ? w0 : (sel == 1) ? w1 : (sel == 2) ? w2 : w3;
        float4 v = ((const float4*)src)[loc];
        size_t o = (size_t)sel * D_MODEL * D_MODEL + 4*(size_t)loc;
        ((__half2*)(g_wh + o))[0] = __floats2half2_rn(v.x*32.f, v.y*32.f);
        ((__half2*)(g_wh + o))[1] = __floats2half2_rn(v.z*32.f, v.w*32.f);
    }
    GDC_LAUNCH();
}

// ---------------- fp16 GEMM: BK=64, 3-stage, SW128, 2 CTAs/SM ----------------
#define TILE_B (128*128)
#define STAGE_B (2*TILE_B)
#define GEMM_SMEM (3*STAGE_B)       /* 98304 */
#define NSTG 16

__device__ __forceinline__ void gemm_body(
    int ep, const __half* __restrict__ Xh,
    const float* __restrict__ bias, float* __restrict__ outp, char* smem)
{
    const uint32_t sb = smem_to_u32(smem);
    const int tid = threadIdx.x;
    const int lane = tid & 31, wid = tid >> 5;
    const int wm = wid & 1, wn = wid >> 1;
    const int m0 = blockIdx.y * 128;
    const int n0 = blockIdx.x * 128;

    const __half* Wh = g_wh + (size_t)ep * D_MODEL * D_MODEL;

    float acc[4][4][4];
    #pragma unroll
    for (int i = 0; i < 4; i++)
        #pragma unroll
        for (int j = 0; j < 4; j++)
            #pragma unroll
            for (int l = 0; l < 4; l++) acc[i][j][l] = 0.f;

    const int lr = tid >> 2, lu = (tid & 3) * 2;
    const uint32_t d00 = SWZ128(lr*128 + lu*16),        d01 = SWZ128(lr*128 + (lu+1)*16);
    const uint32_t d10 = SWZ128((lr+64)*128 + lu*16),   d11 = SWZ128((lr+64)*128 + (lu+1)*16);

    auto load_stage = [&](int buf, int k0) {
        uint32_t base = sb + buf * STAGE_B;
        CP_ASYNC16(base + d00, Xh + (size_t)(m0 + lr)*D_MODEL + k0 + lu*8);
        CP_ASYNC16(base + d01, Xh + (size_t)(m0 + lr)*D_MODEL + k0 + lu*8 + 8);
        CP_ASYNC16(base + d10, Xh + (size_t)(m0 + lr + 64)*D_MODEL + k0 + lu*8);
        CP_ASYNC16(base + d11, Xh + (size_t)(m0 + lr + 64)*D_MODEL + k0 + lu*8 + 8);
        base += TILE_B;
        CP_ASYNC16(base + d00, Wh + (size_t)(n0 + lr)*D_MODEL + k0 + lu*8);
        CP_ASYNC16(base + d01, Wh + (size_t)(n0 + lr)*D_MODEL + k0 + lu*8 + 8);
        CP_ASYNC16(base + d10, Wh + (size_t)(n0 + lr + 64)*D_MODEL + k0 + lu*8);
        CP_ASYNC16(base + d11, Wh + (size_t)(n0 + lr + 64)*D_MODEL + k0 + lu*8 + 8);
        CP_COMMIT();
    };

    GDC_WAIT();                     // predecessor data (g_xh/g_wh or g_ah) must be visible
    load_stage(0, 0);
    load_stage(1, 64);

    for (int kc = 0; kc < NSTG; kc++) {
        if (kc < NSTG-1) { CP_WAIT1(); } else { CP_WAIT0(); }
        __syncthreads();
        if (kc + 2 < NSTG) load_stage((kc + 2) % 3, (kc + 2) * 64);

        const uint32_t base = sb + (kc % 3) * STAGE_B;
        #pragma unroll
        for (int ks = 0; ks < 4; ks++) {
            uint32_t ah[4][4], bh[2][4];
            #pragma unroll
            for (int mt = 0; mt < 4; mt++) {
                const int rA = wm*64 + mt*16 + (lane & 15);
                const uint32_t offA = SWZ128(rA*128 + ((lane >> 4) + 2*ks)*16);
                ldsm4(ah[mt], base + offA);
            }
            #pragma unroll
            for (int op = 0; op < 2; op++) {
                const int rB = wn*32 + op*16 + ((lane >> 4) << 3) + (lane & 7);
                const uint32_t offB = SWZ128(rB*128 + (((lane >> 3) & 1) + 2*ks)*16);
                ldsm4(bh[op], base + TILE_B + offB);
            }
            #pragma unroll
            for (int mt = 0; mt < 4; mt++)
                #pragma unroll
                for (int nt = 0; nt < 4; nt++) {
                    const uint32_t* bhp = &bh[nt >> 1][(nt & 1) * 2];
                    mma16816h(acc[mt][nt], ah[mt], bhp);
                }
        }
    }
    __syncthreads();

    // ---- epilogue (acc is 32x scaled) ----
    const float INV32 = 1.f/32.f;
    const int m_base = m0 + wm*64;
    #pragma unroll
    for (int mt = 0; mt < 4; mt++) {
        #pragma unroll
        for (int nt = 0; nt < 4; nt++) {
            const int n = n0 + wn*32 + nt*8 + (lane & 3)*2;
            const float b0v = bias[n], b1v = bias[n+1];
            #pragma unroll
            for (int half = 0; half < 2; half++) {
                const int m = m_base + mt*16 + (lane >> 2) + half*8;
                float y0 = acc[mt][nt][half*2+0]*INV32 + b0v;
                float y1 = acc[mt][nt][half*2+1]*INV32 + b1v;
                if (ep <= 1) { y0 = phi_fn(y0); y1 = phi_fn(y1); }
                if (ep <= 2) {
                    const int h = n >> 6, d = n & 63;
                    const int b = m >> 11, t = m & (TSEQ-1);
                    const size_t off = ((size_t)((b*N_HEADS + h)*TSEQ + t))*DK + d;
                    __half* dst = (ep == 0) ? g_qf : (ep == 1) ? g_kf : g_vf;
                    *(__half2*)(dst + off) = __floats2half2_rn(y0, y1);
                } else {
                    *(float2*)(outp + (size_t)m*D_MODEL + n) = make_float2(y0, y1);
                }
            }
        }
    }
    GDC_LAUNCH();
}

__global__ __launch_bounds__(256, 2) void gemm_qkv(
    const float* __restrict__ bq, const float* __restrict__ bk,
    const float* __restrict__ bv)
{
    extern __shared__ char smem[];
    const int ep = blockIdx.z;
    const float* bias = (ep == 0) ? bq : (ep == 1) ? bk : bv;
    gemm_body(ep, g_xh, bias, nullptr, smem);
}
__global__ __launch_bounds__(256, 2) void gemm_wo(
    const float* __restrict__ bo, float* __restrict__ outp)
{
    extern __shared__ char smem[];
    gemm_body(3, g_ah, bo, outp, smem);
}

// ================= attention on tensor cores (fp16) =================
#define APITCH 144
#define ATILE (128*APITCH)
#define KVTILE (DK*APITCH)

#define CKV_SMEM (2*ATILE)          /* 36864 */
__global__ __launch_bounds__(128, 4) void chunk_kv_mma()
{
    extern __shared__ char smem[];
    const uint32_t sb = smem_to_u32(smem);
    const uint32_t SK = 0, SV = ATILE;
    const int blk = blockIdx.x;
    const int bh = blk >> 4, c = blk & 15;
    const int tid = threadIdx.x;
    const int lane = tid & 31, wid = tid >> 5;
    const size_t gbase = (size_t)bh*TSEQ*DK + (size_t)c*CHUNK*DK;

    GDC_WAIT();
    #pragma unroll
    for (int it = 0; it < 8; it++) {
        int idx = tid + it*128;
        int r = idx >> 3, cc = idx & 7;
        const size_t so = gbase + (size_t)r*DK + cc*8;
        *(float4*)(smem + SK + r*APITCH + cc*16) = *(const float4*)(g_kf + so);
        *(float4*)(smem + SV + r*APITCH + cc*16) = *(const float4*)(g_vf + so);
    }
    {
        int r = tid;
        *(float4*)(smem + SV + r*APITCH + 128) =
            make_float4(__uint_as_float(0x00003C00u), 0.f, 0.f, 0.f);
    }
    __syncthreads();

    float f[8][4];
    #pragma unroll
    for (int n = 0; n < 8; n++)
        #pragma unroll
        for (int l = 0; l < 4; l++) f[n][l] = 0.f;
    float f8[4] = {0.f, 0.f, 0.f, 0.f};

    const uint32_t ka_rel = (uint32_t)(( ((lane>>4)&1)*8 + (lane&7) )*APITCH
                                       + (wid*16 + ((lane>>3)&1)*8)*2);
    const uint32_t vb_rel = (uint32_t)(( ((lane>>3)&1)*8 + (lane&7) )*APITCH
                                       + ((lane>>4)*8)*2);
    const uint32_t v2_rel = (uint32_t)(( ((lane>>3)&1)*8 + (lane&7) )*APITCH + 64*2);
    #pragma unroll
    for (int ks = 0; ks < 8; ks++) {
        const uint32_t krow = (uint32_t)(ks*16)*APITCH;
        uint32_t kah[4], vb[4][4], v2[2];
        ldsm4t(kah, sb + SK + krow + ka_rel);
        #pragma unroll
        for (int p = 0; p < 4; p++)
            ldsm4t(vb[p], sb + SV + krow + vb_rel + (uint32_t)(p*16*2));
        ldsm2t(v2, sb + SV + krow + v2_rel);
        #pragma unroll
        for (int nt = 0; nt < 8; nt++)
            mma16816h(f[nt], kah, &vb[nt>>1][(nt&1)*2]);
        mma16816h(f8, kah, v2);
    }

    float* kvout = g_kv + (size_t)blk*DK*DK;
    const int d0 = wid*16 + (lane>>2);
    #pragma unroll
    for (int nt = 0; nt < 8; nt++) {
        const int e = nt*8 + (lane&3)*2;
        *(float2*)(kvout + (size_t)d0*DK + e)     = make_float2(f[nt][0], f[nt][1]);
        *(float2*)(kvout + (size_t)(d0+8)*DK + e) = make_float2(f[nt][2], f[nt][3]);
    }
    if ((lane & 3) == 0) {
        g_ksum[(size_t)blk*DK + d0]     = f8[0];
        g_ksum[(size_t)blk*DK + d0 + 8] = f8[2];
    }
    GDC_LAUNCH();
}

// ---------------- exclusive prefix scan ----------------
__global__ __launch_bounds__(256) void chunk_scan_kernel()
{
    const int bh = blockIdx.x;
    const int pos = blockIdx.y * 256 + threadIdx.x;
    if (pos >= DK*KVE) { GDC_WAIT(); GDC_LAUNCH(); return; }
    const int d = pos / KVE, e = pos % KVE;

    GDC_WAIT();
    float vals[NCHUNK];
    #pragma unroll
    for (int c = 0; c < NCHUNK; c++) {
        const size_t blk = (size_t)(bh*NCHUNK + c);
        float v = 0.f;
        if (e < DK)       v = g_kv[blk*DK*DK + (size_t)d*DK + e];
        else if (e == DK) v = g_ksum[blk*DK + d];
        vals[c] = v;
    }
    float run = 0.f;
    #pragma unroll
    for (int c = 0; c < NCHUNK; c++) {
        const size_t blk = (size_t)(bh*NCHUNK + c);
        g_kvf[blk*DK*KVE + pos] = __float2half(run);
        run += vals[c];
    }
    GDC_LAUNCH();
}

// ---------------- per-chunk attention (fp16, causal) ----------------
#define ATT_SMEM (3*ATILE + KVTILE)   /* 64512 */
__global__ __launch_bounds__(256, 2) void attn_mma_kernel()
{
    extern __shared__ char smem[];
    const uint32_t sb = smem_to_u32(smem);
    const uint32_t SQ = 0, SK = ATILE, SV = 2*ATILE;
    const uint32_t SG = 3*ATILE;

    const int blk = blockIdx.x;
    const int bh = blk >> 4, c = blk & 15;
    const int tid = threadIdx.x;
    const int lane = tid & 31, wid = tid >> 5;
    const size_t gbase = (size_t)bh*TSEQ*DK + (size_t)c*CHUNK*DK;

    GDC_WAIT();
    #pragma unroll
    for (int it = 0; it < 4; it++) {
        int idx = tid + it*256;
        int r = idx >> 3, cc = idx & 7;
        const size_t so = gbase + (size_t)r*DK + cc*8;
        const uint32_t doff = r*APITCH + cc*16;
        *(float4*)(smem + SQ + doff) = *(const float4*)(g_qf + so);
        *(float4*)(smem + SK + doff) = *(const float4*)(g_kf + so);
        *(float4*)(smem + SV + doff) = *(const float4*)(g_vf + so);
    }
    if (c > 0) {
        const size_t kvbase = (size_t)blk*DK*KVE;
        for (int idx = tid; idx < 576; idx += 256) {
            int r = idx / 9, cc = idx % 9;
            *(float4*)(smem + SG + r*APITCH + cc*16) =
                *(const float4*)(g_kvf + kvbase + (size_t)r*KVE + cc*8);
        }
    }
    __syncthreads();

    const int rgrp = (wid < 4) ? wid : 11 - wid;
    const int rbase = rgrp * 16;
    const uint32_t qa_rel = (uint32_t)((rbase + (lane & 15))*APITCH + (lane >> 4)*16);
    uint32_t qa[4][4];
    #pragma unroll
    for (int ks = 0; ks < 4; ks++)
        ldsm4(qa[ks], sb + SQ + qa_rel + ks*32);

    float o[9][4];
    #pragma unroll
    for (int n = 0; n < 9; n++)
        #pragma unroll
        for (int l = 0; l < 4; l++) o[n][l] = 0.f;

    if (c > 0) {
        const uint32_t gb_rel = (uint32_t)(( ((lane>>3)&1)*8 + (lane&7) )*APITCH + ((lane>>4)*8)*2);
        const uint32_t g2_rel = (uint32_t)(( ((lane>>3)&1)*8 + (lane&7) )*APITCH + 64*2);
        #pragma unroll
        for (int ks = 0; ks < 4; ks++) {
            const uint32_t krow = (uint32_t)(ks*16)*APITCH;
            uint32_t gb[4][4], g2[2];
            #pragma unroll
            for (int p = 0; p < 4; p++)
                ldsm4t(gb[p], sb + SG + krow + gb_rel + (uint32_t)(p*16*2));
            ldsm2t(g2, sb + SG + krow + g2_rel);
            #pragma unroll
            for (int nt = 0; nt < 8; nt++)
                mma16816h(o[nt], qa[ks], &gb[nt>>1][(nt&1)*2]);
            mma16816h(o[8], qa[ks], g2);
        }
    }

    float zacc0 = 0.f, zacc1 = 0.f;
    const int row0 = rbase + (lane >> 2), row1 = row0 + 8;
    const int ncc = rgrp/2 + 1;
    const uint32_t kb_col = (uint32_t)(((lane>>3)&1)*16);
    const uint32_t vb_rel = (uint32_t)(( ((lane>>3)&1)*8 + (lane&7) )*APITCH + ((lane>>4)*8)*2);

    for (int cc = 0; cc < ncc; cc++) {
        const int c0 = cc*32;
        float s[4][4];
        #pragma unroll
        for (int n = 0; n < 4; n++)
            #pragma unroll
            for (int l = 0; l < 4; l++) s[n][l] = 0.f;
        #pragma unroll
        for (int ks = 0; ks < 4; ks++) {
            uint32_t kb[2][4];
            #pragma unroll
            for (int p = 0; p < 2; p++) {
                const uint32_t kbo = (uint32_t)((c0 + 16*p + ((lane>>4)<<3) + (lane&7))*APITCH)
                                     + kb_col + (uint32_t)(ks*32);
                ldsm4(kb[p], sb + SK + kbo);
            }
            #pragma unroll
            for (int nt = 0; nt < 4; nt++)
                mma16816h(s[nt], qa[ks], &kb[nt>>1][(nt&1)*2]);
        }
        uint32_t af[2][4];
        #pragma unroll
        for (int nt = 0; nt < 4; nt++) {
            const int colj = c0 + nt*8 + (lane&3)*2;
            float e0 = (colj   <= row0) ? s[nt][0] : 0.f;
            float e1 = (colj+1 <= row0) ? s[nt][1] : 0.f;
            float e2 = (colj   <= row1) ? s[nt][2] : 0.f;
            float e3 = (colj+1 <= row1) ? s[nt][3] : 0.f;
            zacc0 += e0 + e1;
            zacc1 += e2 + e3;
            const int kk = nt >> 1, half = nt & 1;
            af[kk][half*2+0] = pack_h(e0, e1);
            af[kk][half*2+1] = pack_h(e2, e3);
        }
        #pragma unroll
        for (int kk = 0; kk < 2; kk++) {
            const uint32_t krow = (uint32_t)((c0 + kk*16))*APITCH;
            uint32_t vb[4][4];
            #pragma unroll
            for (int p = 0; p < 4; p++)
                ldsm4t(vb[p], sb + SV + krow + vb_rel + (uint32_t)(p*16*2));
            #pragma unroll
            for (int nt = 0; nt < 8; nt++)
                mma16816h(o[nt], af[kk], &vb[nt>>1][(nt&1)*2]);
        }
    }

    float z0 = zacc0 + ((lane & 3) == 0 ? o[8][0] : 0.f);
    float z1 = zacc1 + ((lane & 3) == 0 ? o[8][2] : 0.f);
    z0 += __shfl_xor_sync(0xffffffff, z0, 1);
    z0 += __shfl_xor_sync(0xffffffff, z0, 2);
    z1 += __shfl_xor_sync(0xffffffff, z1, 1);
    z1 += __shfl_xor_sync(0xffffffff, z1, 2);
    const float inv0 = 1.f / (z0 + 1e-6f);
    const float inv1 = 1.f / (z1 + 1e-6f);

    const int b = bh >> 4, h = bh & 15;
    const size_t mbase0 = ((size_t)(b*TSEQ + c*CHUNK + row0))*D_MODEL + h*DK;
    const size_t mbase1 = ((size_t)(b*TSEQ + c*CHUNK + row1))*D_MODEL + h*DK;
    #pragma unroll
    for (int nt = 0; nt < 8; nt++) {
        const int e = nt*8 + (lane&3)*2;
        float y0 = o[nt][0]*inv0, y1 = o[nt][1]*inv0;
        float y2 = o[nt][2]*inv1, y3 = o[nt][3]*inv1;
        *(__half2*)(g_ah + mbase0 + e) = __floats2half2_rn(y0, y1);
        *(__half2*)(g_ah + mbase1 + e) = __floats2half2_rn(y2, y3);
    }
    GDC_LAUNCH();
}

// ---------------- launch (PDL on dependent kernels) ----------------
template<typename... Args, typename F>
static inline void launch_pdl(F fn, dim3 grid, dim3 block, size_t shmem, Args... args)
{
    cudaLaunchConfig_t cfg = {};
    cfg.gridDim = grid;
    cfg.blockDim = block;
    cfg.dynamicSmemBytes = shmem;
    cfg.stream = 0;
    cudaLaunchAttribute at[1];
    at[0].id = cudaLaunchAttributeProgrammaticStreamSerialization;
    at[0].val.programmaticStreamSerializationAllowed = 1;
    cfg.attrs = at;
    cfg.numAttrs = 1;
    cudaLaunchKernelEx(&cfg, fn, args...);
}

extern "C" void kernel_launch(void* const* d_in, const int* in_sizes, int n_in,
                              void* d_out, int out_size)
{
    (void)in_sizes; (void)n_in; (void)out_size;
    const float* x  = (const float*)d_in[0];
    const float* Wq = (const float*)d_in[1];
    const float* bq = (const float*)d_in[2];
    const float* Wk = (const float*)d_in[3];
    const float* bk = (const float*)d_in[4];
    const float* Wv = (const float*)d_in[5];
    const float* bv = (const float*)d_in[6];
    const float* Wo = (const float*)d_in[7];
    const float* bo = (const float*)d_in[8];
    float* out = (float*)d_out;

    cudaFuncSetAttribute(gemm_qkv, cudaFuncAttributeMaxDynamicSharedMemorySize, GEMM_SMEM);
    cudaFuncSetAttribute(gemm_wo,  cudaFuncAttributeMaxDynamicSharedMemorySize, GEMM_SMEM);
    cudaFuncSetAttribute(chunk_kv_mma,    cudaFuncAttributeMaxDynamicSharedMemorySize, CKV_SMEM);
    cudaFuncSetAttribute(attn_mma_kernel, cudaFuncAttributeMaxDynamicSharedMemorySize, ATT_SMEM);

    split_all_kernel<<<8192, 256>>>(x, Wq, Wk, Wv, Wo);

    dim3 gq(D_MODEL/128, MROWS/128, 3);   // (8, 32, 3)
    launch_pdl(gemm_qkv, gq, dim3(256), (size_t)GEMM_SMEM, bq, bk, bv);

    launch_pdl(chunk_kv_mma, dim3(NBH*NCHUNK), dim3(128), (size_t)CKV_SMEM);

    dim3 gs(NBH, (DK*KVE + 255)/256);     // (32, 18)
    launch_pdl(chunk_scan_kernel, gs, dim3(256), (size_t)0);

    launch_pdl(attn_mma_kernel, dim3(NBH*NCHUNK), dim3(256), (size_t)ATT_SMEM);

    dim3 go(D_MODEL/128, MROWS/128);      // (8, 32)
    launch_pdl(gemm_wo, go, dim3(256), (size_t)GEMM_SMEM, bo, out);
}